// round 1
// baseline (speedup 1.0000x reference)
#include <cuda_runtime.h>
#include <math.h>

// Problem constants
#define NLAYERS 12
#define BATCH   8
#define SEQ     512
#define HID     768
#define NHEAD   12
#define HDIM    64
#define MROWS   (BATCH * SEQ)      // 4096
#define MH      (MROWS * HID)      // 3,145,728 floats
#define SCELEMS (BATCH * NHEAD * SEQ * SEQ)  // 25,165,824 floats

// Scratch (static device arrays; no allocations allowed)
__device__ float g_X[MH];
__device__ float g_Q[MH];
__device__ float g_K[MH];
__device__ float g_V[MH];
__device__ float g_CTX[MH];
__device__ float g_T1[MH];
__device__ float g_T2[MH];
__device__ float g_SC[SCELEMS];

// ---------------------------------------------------------------------------
// GEMM: C[M,N] = A[M,K] @ W[K,N] + bias[N]   (optional ReLU)
// Tiles: BM=128, BN=128, BK=8; 256 threads; 8x8 accumulators per thread.
// ---------------------------------------------------------------------------
template <bool RELU>
__global__ __launch_bounds__(256)
void gemm_bias_kernel(const float* __restrict__ A,
                      const float* __restrict__ W,
                      const float* __restrict__ bias,
                      float* __restrict__ C,
                      int M, int N, int K) {
    __shared__ float As[8][128];
    __shared__ float Bs[8][128];

    const int tid = threadIdx.x;
    const int blockRow = blockIdx.y * 128;
    const int blockCol = blockIdx.x * 128;

    // A tile loader: 128 rows x 8 cols; one float4 per thread
    const int aRow = tid >> 1;            // 0..127
    const int aCol = (tid & 1) * 4;       // 0 or 4
    // B tile loader: 8 rows x 128 cols; one float4 per thread
    const int bRow = tid >> 5;            // 0..7
    const int bCol = (tid & 31) * 4;      // 0..124

    const int tRow = (tid >> 4) * 8;      // 0..120
    const int tCol = (tid & 15) * 8;      // 0..120

    float acc[8][8];
#pragma unroll
    for (int i = 0; i < 8; i++)
#pragma unroll
        for (int j = 0; j < 8; j++) acc[i][j] = 0.0f;

    const float* Aptr = A + (size_t)(blockRow + aRow) * K;
    const float* Wptr = W + blockCol;

    for (int k0 = 0; k0 < K; k0 += 8) {
        float4 a4 = *reinterpret_cast<const float4*>(Aptr + k0 + aCol);
        As[aCol + 0][aRow] = a4.x;
        As[aCol + 1][aRow] = a4.y;
        As[aCol + 2][aRow] = a4.z;
        As[aCol + 3][aRow] = a4.w;
        float4 b4 = *reinterpret_cast<const float4*>(Wptr + (size_t)(k0 + bRow) * N + bCol);
        *reinterpret_cast<float4*>(&Bs[bRow][bCol]) = b4;
        __syncthreads();

#pragma unroll
        for (int k = 0; k < 8; k++) {
            float4 a0 = *reinterpret_cast<const float4*>(&As[k][tRow]);
            float4 a1 = *reinterpret_cast<const float4*>(&As[k][tRow + 4]);
            float4 b0 = *reinterpret_cast<const float4*>(&Bs[k][tCol]);
            float4 b1 = *reinterpret_cast<const float4*>(&Bs[k][tCol + 4]);
            float ar[8] = {a0.x, a0.y, a0.z, a0.w, a1.x, a1.y, a1.z, a1.w};
            float br[8] = {b0.x, b0.y, b0.z, b0.w, b1.x, b1.y, b1.z, b1.w};
#pragma unroll
            for (int i = 0; i < 8; i++)
#pragma unroll
                for (int j = 0; j < 8; j++)
                    acc[i][j] = fmaf(ar[i], br[j], acc[i][j]);
        }
        __syncthreads();
    }

    const float4 bv0 = *reinterpret_cast<const float4*>(bias + blockCol + tCol);
    const float4 bv1 = *reinterpret_cast<const float4*>(bias + blockCol + tCol + 4);
    const float bb[8] = {bv0.x, bv0.y, bv0.z, bv0.w, bv1.x, bv1.y, bv1.z, bv1.w};

#pragma unroll
    for (int i = 0; i < 8; i++) {
        float* Crow = C + (size_t)(blockRow + tRow + i) * N + blockCol + tCol;
        float4 o0, o1;
        float v;
        v = acc[i][0] + bb[0]; if (RELU) v = fmaxf(v, 0.f); o0.x = v;
        v = acc[i][1] + bb[1]; if (RELU) v = fmaxf(v, 0.f); o0.y = v;
        v = acc[i][2] + bb[2]; if (RELU) v = fmaxf(v, 0.f); o0.z = v;
        v = acc[i][3] + bb[3]; if (RELU) v = fmaxf(v, 0.f); o0.w = v;
        v = acc[i][4] + bb[4]; if (RELU) v = fmaxf(v, 0.f); o1.x = v;
        v = acc[i][5] + bb[5]; if (RELU) v = fmaxf(v, 0.f); o1.y = v;
        v = acc[i][6] + bb[6]; if (RELU) v = fmaxf(v, 0.f); o1.z = v;
        v = acc[i][7] + bb[7]; if (RELU) v = fmaxf(v, 0.f); o1.w = v;
        *reinterpret_cast<float4*>(Crow) = o0;
        *reinterpret_cast<float4*>(Crow + 4) = o1;
    }
}

// ---------------------------------------------------------------------------
// Scores: S[bh, q, k] = dot(Q[bh,q,:], K[bh,k,:]) * 0.125
// One block computes a 64x64 tile. K-dim = 64 fully in smem.
// ---------------------------------------------------------------------------
__global__ __launch_bounds__(256)
void scores_kernel(const float* __restrict__ Q,
                   const float* __restrict__ K,
                   float* __restrict__ SC) {
    const int bh = blockIdx.z;
    const int b = bh / NHEAD, h = bh % NHEAD;
    const int q0 = blockIdx.y * 64;
    const int k0 = blockIdx.x * 64;

    const float* Qh = Q + (size_t)(b * SEQ) * HID + h * HDIM;
    const float* Kh = K + (size_t)(b * SEQ) * HID + h * HDIM;
    float* S = SC + (size_t)bh * SEQ * SEQ;

    __shared__ float Qs[64][68];  // [d][q]
    __shared__ float Ks[64][68];  // [d][k]

    const int tid = threadIdx.x;
    const int lr = tid >> 2;           // 0..63 (row within tile)
    const int ld = (tid & 3) * 16;     // d group start

#pragma unroll
    for (int t = 0; t < 16; t += 4) {
        float4 q4 = *reinterpret_cast<const float4*>(Qh + (size_t)(q0 + lr) * HID + ld + t);
        Qs[ld + t + 0][lr] = q4.x;
        Qs[ld + t + 1][lr] = q4.y;
        Qs[ld + t + 2][lr] = q4.z;
        Qs[ld + t + 3][lr] = q4.w;
        float4 k4 = *reinterpret_cast<const float4*>(Kh + (size_t)(k0 + lr) * HID + ld + t);
        Ks[ld + t + 0][lr] = k4.x;
        Ks[ld + t + 1][lr] = k4.y;
        Ks[ld + t + 2][lr] = k4.z;
        Ks[ld + t + 3][lr] = k4.w;
    }
    __syncthreads();

    const int ty = tid >> 4;   // 0..15
    const int tx = tid & 15;   // 0..15
    float acc[4][4];
#pragma unroll
    for (int i = 0; i < 4; i++)
#pragma unroll
        for (int j = 0; j < 4; j++) acc[i][j] = 0.0f;

#pragma unroll
    for (int d = 0; d < 64; d++) {
        float4 a4 = *reinterpret_cast<const float4*>(&Qs[d][ty * 4]);
        float4 b4 = *reinterpret_cast<const float4*>(&Ks[d][tx * 4]);
        float ar[4] = {a4.x, a4.y, a4.z, a4.w};
        float br[4] = {b4.x, b4.y, b4.z, b4.w};
#pragma unroll
        for (int i = 0; i < 4; i++)
#pragma unroll
            for (int j = 0; j < 4; j++)
                acc[i][j] = fmaf(ar[i], br[j], acc[i][j]);
    }

#pragma unroll
    for (int i = 0; i < 4; i++) {
        float4 o;
        o.x = acc[i][0] * 0.125f;
        o.y = acc[i][1] * 0.125f;
        o.z = acc[i][2] * 0.125f;
        o.w = acc[i][3] * 0.125f;
        *reinterpret_cast<float4*>(S + (size_t)(q0 + ty * 4 + i) * SEQ + k0 + tx * 4) = o;
    }
}

// ---------------------------------------------------------------------------
// Softmax over last dim (512), one block per row.
// ---------------------------------------------------------------------------
__global__ __launch_bounds__(256)
void softmax_kernel(float* __restrict__ SC) {
    float* row = SC + (size_t)blockIdx.x * SEQ;
    const int tid = threadIdx.x;

    float2 v = *reinterpret_cast<float2*>(row + tid * 2);
    __shared__ float red[256];

    red[tid] = fmaxf(v.x, v.y);
    __syncthreads();
#pragma unroll
    for (int s = 128; s > 0; s >>= 1) {
        if (tid < s) red[tid] = fmaxf(red[tid], red[tid + s]);
        __syncthreads();
    }
    const float m = red[0];
    __syncthreads();

    v.x = __expf(v.x - m);
    v.y = __expf(v.y - m);
    red[tid] = v.x + v.y;
    __syncthreads();
#pragma unroll
    for (int s = 128; s > 0; s >>= 1) {
        if (tid < s) red[tid] += red[tid + s];
        __syncthreads();
    }
    const float inv = 1.0f / red[0];
    v.x *= inv;
    v.y *= inv;
    *reinterpret_cast<float2*>(row + tid * 2) = v;
}

// ---------------------------------------------------------------------------
// Context: CTX[bh, q, :] = P[bh, q, :] @ V[bh, :, :]   (per head, 512x512 @ 512x64)
// Block computes 64 q-rows x 64 d-cols; iterates kk in chunks of 64.
// ---------------------------------------------------------------------------
__global__ __launch_bounds__(256)
void ctx_kernel(const float* __restrict__ SC,
                const float* __restrict__ V,
                float* __restrict__ CTX) {
    const int bh = blockIdx.z;
    const int b = bh / NHEAD, h = bh % NHEAD;
    const int q0 = blockIdx.y * 64;

    const float* S = SC + (size_t)bh * SEQ * SEQ;
    const float* Vh = V + (size_t)(b * SEQ) * HID + h * HDIM;
    float* Ch = CTX + (size_t)(b * SEQ) * HID + h * HDIM;

    __shared__ float Ps[64][68];  // [kk][q] (transposed)
    __shared__ float Vs[64][68];  // [kk][d]

    const int tid = threadIdx.x;
    const int lr = tid >> 2;
    const int ld = (tid & 3) * 16;
    const int ty = tid >> 4;
    const int tx = tid & 15;

    float acc[4][4];
#pragma unroll
    for (int i = 0; i < 4; i++)
#pragma unroll
        for (int j = 0; j < 4; j++) acc[i][j] = 0.0f;

    for (int kk0 = 0; kk0 < SEQ; kk0 += 64) {
#pragma unroll
        for (int t = 0; t < 16; t += 4) {
            float4 p4 = *reinterpret_cast<const float4*>(S + (size_t)(q0 + lr) * SEQ + kk0 + ld + t);
            Ps[ld + t + 0][lr] = p4.x;
            Ps[ld + t + 1][lr] = p4.y;
            Ps[ld + t + 2][lr] = p4.z;
            Ps[ld + t + 3][lr] = p4.w;
            float4 v4 = *reinterpret_cast<const float4*>(Vh + (size_t)(kk0 + lr) * HID + ld + t);
            *reinterpret_cast<float4*>(&Vs[lr][ld + t]) = v4;
        }
        __syncthreads();

#pragma unroll
        for (int kk = 0; kk < 64; kk++) {
            float4 a4 = *reinterpret_cast<const float4*>(&Ps[kk][ty * 4]);
            float4 b4 = *reinterpret_cast<const float4*>(&Vs[kk][tx * 4]);
            float ar[4] = {a4.x, a4.y, a4.z, a4.w};
            float br[4] = {b4.x, b4.y, b4.z, b4.w};
#pragma unroll
            for (int i = 0; i < 4; i++)
#pragma unroll
                for (int j = 0; j < 4; j++)
                    acc[i][j] = fmaf(ar[i], br[j], acc[i][j]);
        }
        __syncthreads();
    }

#pragma unroll
    for (int i = 0; i < 4; i++) {
        float4 o = {acc[i][0], acc[i][1], acc[i][2], acc[i][3]};
        *reinterpret_cast<float4*>(Ch + (size_t)(q0 + ty * 4 + i) * HID + tx * 4) = o;
    }
}

// ---------------------------------------------------------------------------
// Add + LayerNorm: O[row,:] = LN(X[row,:] + Y[row,:]) * g + b
// One block (256 threads) per row of 768.
// ---------------------------------------------------------------------------
__global__ __launch_bounds__(256)
void add_ln_kernel(const float* __restrict__ X,
                   const float* __restrict__ Y,
                   const float* __restrict__ g,
                   const float* __restrict__ b,
                   float* __restrict__ O) {
    const int row = blockIdx.x;
    const float* xr = X + (size_t)row * HID;
    const float* yr = Y + (size_t)row * HID;
    float* orow = O + (size_t)row * HID;
    const int tid = threadIdx.x;

    float vals[3];
    float s = 0.f, ss = 0.f;
#pragma unroll
    for (int t = 0; t < 3; t++) {
        const int c = tid + t * 256;
        float v = xr[c] + yr[c];
        vals[t] = v;
        s += v;
        ss += v * v;
    }

    __shared__ float rs[256];
    __shared__ float rss[256];
    rs[tid] = s;
    rss[tid] = ss;
    __syncthreads();
#pragma unroll
    for (int st = 128; st > 0; st >>= 1) {
        if (tid < st) {
            rs[tid] += rs[tid + st];
            rss[tid] += rss[tid + st];
        }
        __syncthreads();
    }
    const float mean = rs[0] * (1.0f / HID);
    const float var = rss[0] * (1.0f / HID) - mean * mean;
    const float inv = rsqrtf(var + 1e-12f);

#pragma unroll
    for (int t = 0; t < 3; t++) {
        const int c = tid + t * 256;
        orow[c] = (vals[t] - mean) * inv * g[c] + b[c];
    }
}

// ---------------------------------------------------------------------------
// Launch
// ---------------------------------------------------------------------------
extern "C" void kernel_launch(void* const* d_in, const int* in_sizes, int n_in,
                              void* d_out, int out_size) {
    const float* x    = (const float*)d_in[0];
    const float* Wq   = (const float*)d_in[1];
    const float* bq   = (const float*)d_in[2];
    const float* Wk   = (const float*)d_in[3];
    const float* bk   = (const float*)d_in[4];
    const float* Wv   = (const float*)d_in[5];
    const float* bv   = (const float*)d_in[6];
    const float* Wo   = (const float*)d_in[7];
    const float* bo   = (const float*)d_in[8];
    const float* g1   = (const float*)d_in[9];
    const float* be1  = (const float*)d_in[10];
    const float* W2   = (const float*)d_in[11];
    const float* b2   = (const float*)d_in[12];
    const float* g2   = (const float*)d_in[13];
    const float* be2  = (const float*)d_in[14];

    float *X, *Q, *K, *V, *CTX, *T1, *T2, *SC;
    cudaGetSymbolAddress((void**)&X,   g_X);
    cudaGetSymbolAddress((void**)&Q,   g_Q);
    cudaGetSymbolAddress((void**)&K,   g_K);
    cudaGetSymbolAddress((void**)&V,   g_V);
    cudaGetSymbolAddress((void**)&CTX, g_CTX);
    cudaGetSymbolAddress((void**)&T1,  g_T1);
    cudaGetSymbolAddress((void**)&T2,  g_T2);
    cudaGetSymbolAddress((void**)&SC,  g_SC);

    cudaMemcpyAsync(X, x, (size_t)MH * sizeof(float), cudaMemcpyDeviceToDevice);

    const dim3 gemmGrid(HID / 128, MROWS / 128);  // (6, 32)
    const dim3 scGrid(SEQ / 64, SEQ / 64, BATCH * NHEAD);  // (8, 8, 96)
    const dim3 ctxGrid(1, SEQ / 64, BATCH * NHEAD);        // (1, 8, 96)

    for (int l = 0; l < NLAYERS; l++) {
        const size_t wo = (size_t)l * HID * HID;
        const size_t vo = (size_t)l * HID;

        gemm_bias_kernel<false><<<gemmGrid, 256>>>(X, Wq + wo, bq + vo, Q, MROWS, HID, HID);
        gemm_bias_kernel<false><<<gemmGrid, 256>>>(X, Wk + wo, bk + vo, K, MROWS, HID, HID);
        gemm_bias_kernel<false><<<gemmGrid, 256>>>(X, Wv + wo, bv + vo, V, MROWS, HID, HID);

        scores_kernel<<<scGrid, 256>>>(Q, K, SC);
        softmax_kernel<<<BATCH * NHEAD * SEQ, 256>>>(SC);
        ctx_kernel<<<ctxGrid, 256>>>(SC, V, CTX);

        gemm_bias_kernel<false><<<gemmGrid, 256>>>(CTX, Wo + wo, bo + vo, T1, MROWS, HID, HID);
        add_ln_kernel<<<MROWS, 256>>>(X, T1, g1 + vo, be1 + vo, T2);

        gemm_bias_kernel<true><<<gemmGrid, 256>>>(T2, W2 + wo, b2 + vo, T1, MROWS, HID, HID);
        gemm_bias_kernel<true><<<gemmGrid, 256>>>(T1, W2 + wo, b2 + vo, Q, MROWS, HID, HID);
        add_ln_kernel<<<MROWS, 256>>>(T2, Q, g2 + vo, be2 + vo, X);
    }

    cudaMemcpyAsync(d_out, X, (size_t)MH * sizeof(float), cudaMemcpyDeviceToDevice);
}